// round 4
// baseline (speedup 1.0000x reference)
#include <cuda_runtime.h>

#define NN 100000   // nodes
#define NE 1600000  // edges
#define NF 128      // input features
#define NH 64       // hidden
#define NC 10       // classes
#define NL 3        // layers
#define NG 1000     // graphs

typedef unsigned long long u64;

// Scratch (device globals: no allocation allowed in kernel_launch)
__device__ float g_h[NN * NH];
__device__ float g_agg[NN * NH];
__device__ float g_t[NN * NH];
__device__ float g_pool[NG * NH];
__device__ float g_g2[NG * NH];

// ---------------------------------------------------------------------------
// Packed f32x2 helpers (Blackwell FFMA2 — PTX-only)
// ---------------------------------------------------------------------------
__device__ __forceinline__ u64 pack_dup(float x) {
    u64 r;
    asm("mov.b64 %0, {%1, %1};" : "=l"(r) : "f"(x));
    return r;
}
__device__ __forceinline__ void fma2(u64& d, u64 a, u64 b) {
    asm("fma.rn.f32x2 %0, %1, %2, %0;" : "+l"(d) : "l"(a), "l"(b));
}
__device__ __forceinline__ void unpack2(float& lo, float& hi, u64 v) {
    asm("mov.b64 {%0, %1}, %2;" : "=f"(lo), "=f"(hi) : "l"(v));
}

// ---------------------------------------------------------------------------
// zero: float4 grid-stride
// ---------------------------------------------------------------------------
__global__ void zero_kernel(float* __restrict__ p, int n4) {
    float4 z = make_float4(0.f, 0.f, 0.f, 0.f);
    for (int i = blockIdx.x * blockDim.x + threadIdx.x; i < n4;
         i += gridDim.x * blockDim.x)
        reinterpret_cast<float4*>(p)[i] = z;
}

// ---------------------------------------------------------------------------
// GEMM: out[N,64] = act( (A [+ A2]) [N,K] @ W [K,64] + b )
// Block 256 threads, 128 rows/block. Register tile: 4 rows x 8 cols / thread,
// columns packed in pairs -> fma.rn.f32x2 (16 FMA2 per k vs 32 FFMA).
// ---------------------------------------------------------------------------
template <int K, bool RELU, bool ADD2>
__global__ __launch_bounds__(256)
void gemm_kernel(const float* __restrict__ A,
                 const float* __restrict__ A2,
                 const float* __restrict__ W,
                 const float* __restrict__ bias,
                 float* __restrict__ out, int N) {
    constexpr int ROWS = 128;
    constexpr int STR  = K + 1;  // bank-conflict pad

    extern __shared__ float sm[];
    float* Ws = sm;            // K * 64
    float* As = sm + K * 64;   // ROWS * STR

    const int tid  = threadIdx.x;
    const int row0 = blockIdx.x * ROWS;

    // Stage W (coalesced)
    for (int i = tid; i < K * 64; i += 256) Ws[i] = W[i];

    // Stage A tile (coalesced), fold in A2 (= h + agg) if requested
    for (int i = tid; i < ROWS * K; i += 256) {
        int r = i / K, k = i - r * K;
        int gr = row0 + r;
        float v = 0.f;
        if (gr < N) {
            size_t gi = (size_t)gr * K + k;
            v = A[gi];
            if (ADD2) v += A2[gi];
        }
        As[r * STR + k] = v;
    }
    __syncthreads();

    const int cb = (tid & 7) * 8;    // column base (8 cols = 4 packed pairs)
    const int r0 = (tid >> 3) * 4;   // row base    (4 rows)

    const u64* Ws2 = reinterpret_cast<const u64*>(Ws);  // [k*32 + c/2]
    const int wb = cb >> 1;

    u64 acc[4][4];
    #pragma unroll
    for (int j = 0; j < 4; j++)
        #pragma unroll
        for (int c = 0; c < 4; c++) acc[j][c] = 0ull;

    #pragma unroll 8
    for (int k = 0; k < K; k++) {
        const u64* wrow = Ws2 + k * 32 + wb;
        u64 w0 = wrow[0];
        u64 w1 = wrow[1];
        u64 w2 = wrow[2];
        u64 w3 = wrow[3];
        #pragma unroll
        for (int j = 0; j < 4; j++) {
            u64 a = pack_dup(As[(r0 + j) * STR + k]);
            fma2(acc[j][0], a, w0);
            fma2(acc[j][1], a, w1);
            fma2(acc[j][2], a, w2);
            fma2(acc[j][3], a, w3);
        }
    }

    const float4 b0 = *reinterpret_cast<const float4*>(bias + cb);
    const float4 b1 = *reinterpret_cast<const float4*>(bias + cb + 4);

    #pragma unroll
    for (int j = 0; j < 4; j++) {
        int gr = row0 + r0 + j;
        if (gr >= N) break;
        float v[8];
        unpack2(v[0], v[1], acc[j][0]);
        unpack2(v[2], v[3], acc[j][1]);
        unpack2(v[4], v[5], acc[j][2]);
        unpack2(v[6], v[7], acc[j][3]);
        float4 o0, o1;
        o0.x = v[0] + b0.x; o0.y = v[1] + b0.y;
        o0.z = v[2] + b0.z; o0.w = v[3] + b0.w;
        o1.x = v[4] + b1.x; o1.y = v[5] + b1.y;
        o1.z = v[6] + b1.z; o1.w = v[7] + b1.w;
        if (RELU) {
            o0.x = fmaxf(o0.x, 0.f); o0.y = fmaxf(o0.y, 0.f);
            o0.z = fmaxf(o0.z, 0.f); o0.w = fmaxf(o0.w, 0.f);
            o1.x = fmaxf(o1.x, 0.f); o1.y = fmaxf(o1.y, 0.f);
            o1.z = fmaxf(o1.z, 0.f); o1.w = fmaxf(o1.w, 0.f);
        }
        float4* op = reinterpret_cast<float4*>(out + (size_t)gr * 64 + cb);
        op[0] = o0;
        op[1] = o1;
    }
}

// ---------------------------------------------------------------------------
// Vector reduction: red.global.add.v4.f32 (sm_90+)
// ---------------------------------------------------------------------------
__device__ __forceinline__ void red_add_v4(float* p, float4 v) {
    asm volatile("red.global.add.v4.f32 [%0], {%1, %2, %3, %4};"
                 :: "l"(p), "f"(v.x), "f"(v.y), "f"(v.z), "f"(v.w)
                 : "memory");
}

// ---------------------------------------------------------------------------
// Edge scatter: agg[dst] += h[src].  Half-warp per edge, float4 per lane.
// ---------------------------------------------------------------------------
__global__ void scatter_kernel(const float* __restrict__ h,
                               const int* __restrict__ ei,
                               float* __restrict__ agg) {
    int warp = blockIdx.x * 8 + (threadIdx.x >> 5);
    int lane = threadIdx.x & 31;
    int e = warp * 2 + (lane >> 4);
    if (e >= NE) return;
    int l16 = lane & 15;
    int s = __ldg(ei + e);        // src
    int d = __ldg(ei + NE + e);   // dst
    if ((unsigned)s >= NN || (unsigned)d >= NN) return;  // defensive
    float4 v = reinterpret_cast<const float4*>(h + (size_t)s * NH)[l16];
    red_add_v4(agg + (size_t)d * NH + l16 * 4, v);
}

// ---------------------------------------------------------------------------
// Global add pool: pool[batch[n]] += h[n].  Half-warp per node.
// ---------------------------------------------------------------------------
__global__ void pool_kernel(const float* __restrict__ h,
                            const int* __restrict__ batch,
                            float* __restrict__ pool) {
    int warp = blockIdx.x * 8 + (threadIdx.x >> 5);
    int lane = threadIdx.x & 31;
    int n = warp * 2 + (lane >> 4);
    if (n >= NN) return;
    int l16 = lane & 15;
    int g = __ldg(batch + n);
    if ((unsigned)g >= NG) return;  // defensive
    float4 v = reinterpret_cast<const float4*>(h + (size_t)n * NH)[l16];
    red_add_v4(pool + (size_t)g * NH + l16 * 4, v);
}

// ---------------------------------------------------------------------------
// Readout: logits = g2 @ roW + rob; out = log_softmax(logits).
// ---------------------------------------------------------------------------
__global__ void readout_kernel(const float* __restrict__ g2,
                               const float* __restrict__ roW,
                               const float* __restrict__ rob,
                               float* __restrict__ out) {
    int row = blockIdx.x * 8 + (threadIdx.x >> 5);
    if (row >= NG) return;
    int lane = threadIdx.x & 31;

    float acc = 0.f;
    if (lane < NC) {
        acc = rob[lane];
        #pragma unroll
        for (int k = 0; k < NH; k++)
            acc = fmaf(g2[(size_t)row * NH + k], roW[k * NC + lane], acc);
    }
    float m = (lane < NC) ? acc : -3.4e38f;
    #pragma unroll
    for (int o = 16; o > 0; o >>= 1)
        m = fmaxf(m, __shfl_xor_sync(0xffffffffu, m, o));
    float e = (lane < NC) ? expf(acc - m) : 0.f;
    float s = e;
    #pragma unroll
    for (int o = 16; o > 0; o >>= 1)
        s += __shfl_xor_sync(0xffffffffu, s, o);
    if (lane < NC) out[(size_t)row * NC + lane] = acc - m - logf(s);
}

// ---------------------------------------------------------------------------
extern "C" void kernel_launch(void* const* d_in, const int* in_sizes, int n_in,
                              void* d_out, int out_size) {
    const float* x      = (const float*)d_in[0];
    const int*   ei     = (const int*)d_in[1];
    const int*   batch  = (const int*)d_in[2];
    const float* pre_w  = (const float*)d_in[3];
    const float* pre_b  = (const float*)d_in[4];
    const float* w1     = (const float*)d_in[5];   // [3,64,64]
    const float* b1     = (const float*)d_in[6];   // [3,64]
    const float* w2     = (const float*)d_in[7];
    const float* b2     = (const float*)d_in[8];
    const float* post_w = (const float*)d_in[9];
    const float* post_b = (const float*)d_in[10];
    const float* ro_w   = (const float*)d_in[11];
    const float* ro_b   = (const float*)d_in[12];
    float*       out    = (float*)d_out;

    float *hP, *aggP, *tP, *poolP, *g2P;
    cudaGetSymbolAddress((void**)&hP,    g_h);
    cudaGetSymbolAddress((void**)&aggP,  g_agg);
    cudaGetSymbolAddress((void**)&tP,    g_t);
    cudaGetSymbolAddress((void**)&poolP, g_pool);
    cudaGetSymbolAddress((void**)&g2P,   g_g2);

    // Dynamic smem sizes
    const int smem_pre = (NF * 64 + 128 * (NF + 1)) * 4;  // 98816 B
    const int smem_hid = (NH * 64 + 128 * (NH + 1)) * 4;  // 49664 B
    cudaFuncSetAttribute(gemm_kernel<NF, false, false>,
                         cudaFuncAttributeMaxDynamicSharedMemorySize, smem_pre);
    cudaFuncSetAttribute(gemm_kernel<NH, true, true>,
                         cudaFuncAttributeMaxDynamicSharedMemorySize, smem_hid);
    cudaFuncSetAttribute(gemm_kernel<NH, true, false>,
                         cudaFuncAttributeMaxDynamicSharedMemorySize, smem_hid);

    // h = x @ pre_w + pre_b
    gemm_kernel<NF, false, false><<<(NN + 127) / 128, 256, smem_pre>>>(
        x, nullptr, pre_w, pre_b, hP, NN);

    for (int l = 0; l < NL; l++) {
        zero_kernel<<<2048, 256>>>(aggP, NN * NH / 4);
        scatter_kernel<<<(NE / 2 + 7) / 8, 256>>>(hP, ei, aggP);
        // t = relu((h + agg) @ w1 + b1)
        gemm_kernel<NH, true, true><<<(NN + 127) / 128, 256, smem_hid>>>(
            hP, aggP, w1 + l * NH * NH, b1 + l * NH, tP, NN);
        // h = relu(t @ w2 + b2)
        gemm_kernel<NH, true, false><<<(NN + 127) / 128, 256, smem_hid>>>(
            tP, nullptr, w2 + l * NH * NH, b2 + l * NH, hP, NN);
    }

    zero_kernel<<<64, 256>>>(poolP, NG * NH / 4);
    pool_kernel<<<(NN / 2 + 7) / 8, 256>>>(hP, batch, poolP);
    // g2 = relu(pool @ post_w + post_b)
    gemm_kernel<NH, true, false><<<(NG + 127) / 128, 256, smem_hid>>>(
        poolP, nullptr, post_w, post_b, g2P, NG);
    readout_kernel<<<(NG + 7) / 8, 256>>>(g2P, ro_w, ro_b, out);
}